// round 13
// baseline (speedup 1.0000x reference)
#include <cuda_runtime.h>

// Problem shape
#define TT 512
#define II 10
#define HH 32
#define EE 16                // batch elements per block (two MMA N=8 tiles)
#define CH 16                // timesteps per x chunk
#define NCH (TT / CH)        // 32
#define XPAD 16              // padded feature dim (K for x part)
#define ESTR (CH * XPAD + 4) // x elem stride in floats (+4: bank skew)

typedef unsigned uu;

__device__ __forceinline__ uu tf32r(float f) {
    uu u; asm("cvt.rna.tf32.f32 %0, %1;" : "=r"(u) : "f"(f)); return u;
}
__device__ __forceinline__ float tanha(float x) {
    float r; asm("tanh.approx.f32 %0, %1;" : "=f"(r) : "f"(x)); return r;
}
// D += A(16x8) * B(8x8), tf32 inputs, fp32 accum (accumulate in place)
__device__ __forceinline__ void mma8(float& d0, float& d1, float& d2, float& d3,
                                     uu a0, uu a1, uu a2, uu a3, uu b0, uu b1) {
    asm("mma.sync.aligned.m16n8k8.row.col.f32.tf32.tf32.f32 "
        "{%0,%1,%2,%3},{%4,%5,%6,%7},{%8,%9},{%0,%1,%2,%3};"
        : "+f"(d0), "+f"(d1), "+f"(d2), "+f"(d3)
        : "r"(a0), "r"(a1), "r"(a2), "r"(a3), "r"(b0), "r"(b1));
}
__device__ __forceinline__ unsigned sm32(const void* p) {
    return (unsigned)__cvta_generic_to_shared(p);
}
__device__ __forceinline__ void cp8(unsigned d, const void* s) {
    asm volatile("cp.async.ca.shared.global [%0], [%1], 8;" :: "r"(d), "l"(s));
}

// 128 threads, 16 elements/block, 2 blocks/SM (single wave for 256 CTAs).
// Warp w computes gate w (rows 32w..32w+31) for all 16 elements via two N=8
// tf32 MMA tiles sharing the same resident weight fragments.
// h compensated on B side (hi+lo); x tf32-hi only.
__global__ void __launch_bounds__(128, 2) lstm_kernel(
    const float* __restrict__ x,     const float* __restrict__ h0,
    const float* __restrict__ c0,    const float* __restrict__ W_ih,
    const float* __restrict__ W_hh,  const float* __restrict__ b_ih,
    const float* __restrict__ b_hh,  const float* __restrict__ W_lin,
    const float* __restrict__ b_lin, float* __restrict__ out)
{
    __shared__ __align__(16) float x_sh[2][EE * ESTR];     // 33.3 KB
    __shared__ __align__(16) uint4 hfrag_sh[2][4][32];     // 4 KB (per n-tile)
    __shared__ __align__(16) float gates_sh[4][HH][EE];    // 8 KB

    const int tid  = threadIdx.x;
    const int w    = tid >> 5;          // warp = gate (0=i,1=f,2=g,3=o)
    const int lane = tid & 31;
    const int gid  = lane >> 2;         // MMA groupID (0..7)
    const int tig  = lane & 3;          // MMA thread-in-group
    const int base = blockIdx.x * EE;

    const float s     = (w == 2) ? 1.0f : 0.5f;
    const float alpha = (w == 2) ? 1.0f : 0.5f;
    const float beta  = (w == 2) ? 0.0f : 0.5f;

    // ---- resident A fragments: W_hh (K=32), W_ih (K=16 padded), tf32-hi ----
    uu ah[2][4][4];                      // [m-tile][k-chunk][a-reg]
    uu ax[2][2][4];
    float bv[2][2];
    #pragma unroll
    for (int mt = 0; mt < 2; mt++) {
        #pragma unroll
        for (int rg = 0; rg < 4; rg++) {
            int row = 32 * w + 16 * mt + 8 * (rg & 1) + gid;
            #pragma unroll
            for (int kc = 0; kc < 4; kc++)
                ah[mt][kc][rg] = tf32r(W_hh[row * HH + 8 * kc + 4 * (rg >> 1) + tig] * s);
            #pragma unroll
            for (int kc = 0; kc < 2; kc++) {
                int j = 8 * kc + 4 * (rg >> 1) + tig;
                ax[mt][kc][rg] = tf32r((j < II) ? W_ih[row * II + j] * s : 0.0f);
            }
        }
        int r0 = 32 * w + 16 * mt + gid;
        bv[mt][0] = (b_ih[r0]     + b_hh[r0])     * s;
        bv[mt][1] = (b_ih[r0 + 8] + b_hh[r0 + 8]) * s;
    }

    // ---- per-thread state: 4 states (rows l2+8m) of element e2 ----
    const int e2 = tid & 15;            // element 0..15
    const int l2 = tid >> 4;            // 0..7
    float cr[4], hr[4];
    #pragma unroll
    for (int m = 0; m < 4; m++) {
        cr[m] = c0[(base + e2) * HH + l2 + 8 * m];
        hr[m] = h0[(base + e2) * HH + l2 + 8 * m];
    }
    float wl[4];
    #pragma unroll
    for (int m = 0; m < 4; m++) wl[m] = W_lin[l2 + 8 * m];

    // h fragment write pointers: value k=l2+8m of element e2 lives at
    // hfrag_sh[e2>>3][m][(e2&7)*4 + (l2&3)], 8-byte slot (l2>>2).
    const int setE  = e2 >> 3;
    const int laneS = (e2 & 7) * 4 + (l2 & 3);
    const int slotA = (l2 >> 2) & 1;
    uint2* hw[4];
    #pragma unroll
    for (int m = 0; m < 4; m++)
        hw[m] = reinterpret_cast<uint2*>(
            reinterpret_cast<char*>(&hfrag_sh[setE][m][laneS]) + slotA * 8);

    #pragma unroll
    for (int m = 0; m < 4; m++) {   // initial h fragments
        uu p = tf32r(hr[m]);
        *hw[m] = make_uint2(p, __float_as_uint(hr[m] - __uint_as_float(p)));
    }

    // ---- x prefetch ----
    #define PREFETCH(chunk, buf)                                                  \
        do {                                                                      \
            for (int p = tid; p < EE * CH * 5; p += 128) {                        \
                int pe = p / (CH * 5);                                            \
                int r2 = p - pe * (CH * 5);                                       \
                int t  = r2 / 5;                                                  \
                int pj = r2 - t * 5;                                              \
                const float* src = x + ((size_t)(base + pe) * TT +                \
                                        (chunk) * CH + t) * II + 2 * pj;          \
                cp8(sm32(&x_sh[buf][pe * ESTR + t * XPAD + 2 * pj]), src);        \
            }                                                                     \
            asm volatile("cp.async.commit_group;");                               \
        } while (0)

    PREFETCH(0, 0);
    // zero pad columns j=10..15 in both buffers
    for (int p = tid; p < 2 * EE * CH * 6; p += 128) {
        int bf = p / (EE * CH * 6);
        int r  = p - bf * (EE * CH * 6);
        int pe = r / (CH * 6);
        int r2 = r - pe * (CH * 6);
        int t  = r2 / 6;
        int jj = 10 + (r2 - t * 6);
        x_sh[bf][pe * ESTR + t * XPAD + jj] = 0.0f;
    }
    asm volatile("cp.async.wait_group 0;");
    __syncthreads();

    // ---- recurrence ----
    for (int cix = 0; cix < NCH; cix++) {
        if (cix + 1 < NCH) { PREFETCH(cix + 1, (cix + 1) & 1); }
        const float* xc = x_sh[cix & 1];

        for (int tt = 0; tt < CH; tt++) {
            // fragments for both n-tiles (conflict-free LDS.128 / LDS.32)
            uint4 hf0[4], hf1[4];
            #pragma unroll
            for (int kc = 0; kc < 4; kc++) {
                hf0[kc] = hfrag_sh[0][kc][lane];
                hf1[kc] = hfrag_sh[1][kc][lane];
            }
            const float* xe0 = xc + gid * ESTR + tt * XPAD;
            const float* xe1 = xc + (8 + gid) * ESTR + tt * XPAD;
            uu bx0[4], bx1[4];
            #pragma unroll
            for (int kc = 0; kc < 2; kc++) {
                bx0[2 * kc]     = tf32r(xe0[8 * kc + tig]);
                bx0[2 * kc + 1] = tf32r(xe0[8 * kc + tig + 4]);
                bx1[2 * kc]     = tf32r(xe1[8 * kc + tig]);
                bx1[2 * kc + 1] = tf32r(xe1[8 * kc + tig + 4]);
            }

            #pragma unroll
            for (int mt = 0; mt < 2; mt++) {
                // n-tile 0 chains
                float ca0 = bv[mt][0], ca1 = bv[mt][0];
                float ca2 = bv[mt][1], ca3 = bv[mt][1];
                float cb0 = 0.f, cb1 = 0.f, cb2 = 0.f, cb3 = 0.f;
                // n-tile 1 chains
                float da0 = bv[mt][0], da1 = bv[mt][0];
                float da2 = bv[mt][1], da3 = bv[mt][1];
                float db0 = 0.f, db1 = 0.f, db2 = 0.f, db3 = 0.f;

                #pragma unroll
                for (int kc = 0; kc < 4; kc++) {
                    mma8(ca0, ca1, ca2, ca3,
                         ah[mt][kc][0], ah[mt][kc][1], ah[mt][kc][2], ah[mt][kc][3],
                         hf0[kc].x, hf0[kc].z);
                    mma8(cb0, cb1, cb2, cb3,
                         ah[mt][kc][0], ah[mt][kc][1], ah[mt][kc][2], ah[mt][kc][3],
                         hf0[kc].y, hf0[kc].w);
                    mma8(da0, da1, da2, da3,
                         ah[mt][kc][0], ah[mt][kc][1], ah[mt][kc][2], ah[mt][kc][3],
                         hf1[kc].x, hf1[kc].z);
                    mma8(db0, db1, db2, db3,
                         ah[mt][kc][0], ah[mt][kc][1], ah[mt][kc][2], ah[mt][kc][3],
                         hf1[kc].y, hf1[kc].w);
                }
                #pragma unroll
                for (int kc = 0; kc < 2; kc++) {
                    mma8(ca0, ca1, ca2, ca3,
                         ax[mt][kc][0], ax[mt][kc][1], ax[mt][kc][2], ax[mt][kc][3],
                         bx0[2 * kc], bx0[2 * kc + 1]);
                    mma8(da0, da1, da2, da3,
                         ax[mt][kc][0], ax[mt][kc][1], ax[mt][kc][2], ax[mt][kc][3],
                         bx1[2 * kc], bx1[2 * kc + 1]);
                }

                int row0 = 16 * mt + gid;
                {
                    float d0 = ca0 + cb0, d1 = ca1 + cb1;
                    float d2 = ca2 + cb2, d3 = ca3 + cb3;
                    *reinterpret_cast<float2*>(&gates_sh[w][row0][2 * tig]) =
                        make_float2(fmaf(alpha, tanha(d0), beta),
                                    fmaf(alpha, tanha(d1), beta));
                    *reinterpret_cast<float2*>(&gates_sh[w][row0 + 8][2 * tig]) =
                        make_float2(fmaf(alpha, tanha(d2), beta),
                                    fmaf(alpha, tanha(d3), beta));
                }
                {
                    float d0 = da0 + db0, d1 = da1 + db1;
                    float d2 = da2 + db2, d3 = da3 + db3;
                    *reinterpret_cast<float2*>(&gates_sh[w][row0][8 + 2 * tig]) =
                        make_float2(fmaf(alpha, tanha(d0), beta),
                                    fmaf(alpha, tanha(d1), beta));
                    *reinterpret_cast<float2*>(&gates_sh[w][row0 + 8][8 + 2 * tig]) =
                        make_float2(fmaf(alpha, tanha(d2), beta),
                                    fmaf(alpha, tanha(d3), beta));
                }
            }
            __syncthreads();   // bar1: gates ready; all h reads complete

            // elementwise update: 4 states (l2+8m, e2)
            #pragma unroll
            for (int m = 0; m < 4; m++) {
                int row = l2 + 8 * m;
                float iv = gates_sh[0][row][e2], fv = gates_sh[1][row][e2];
                float gv = gates_sh[2][row][e2], ov = gates_sh[3][row][e2];
                cr[m] = fmaf(fv, cr[m], iv * gv);
                hr[m] = ov * tanha(cr[m]);
                uu p = tf32r(hr[m]);
                *hw[m] = make_uint2(p, __float_as_uint(hr[m] - __uint_as_float(p)));
            }
            __syncthreads();   // bar2: new h visible
        }
        asm volatile("cp.async.wait_group 0;");
        __syncthreads();
    }

    // ---- final linear head ----
    float* scratch = &gates_sh[0][0][0];      // reuse as [EE][8]
    {
        float partial = 0.0f;
        #pragma unroll
        for (int m = 0; m < 4; m++) partial = fmaf(hr[m], wl[m], partial);
        scratch[e2 * 8 + l2] = partial;
    }
    __syncthreads();
    if (tid < EE) {
        float sum = b_lin[0];
        #pragma unroll
        for (int q = 0; q < 8; q++) sum += scratch[tid * 8 + q];
        out[base + tid] = sum;
    }
}

extern "C" void kernel_launch(void* const* d_in, const int* in_sizes, int n_in,
                              void* d_out, int out_size) {
    const float* x     = (const float*)d_in[0];
    const float* h0    = (const float*)d_in[1];
    const float* c0    = (const float*)d_in[2];
    const float* W_ih  = (const float*)d_in[3];
    const float* W_hh  = (const float*)d_in[4];
    const float* b_ih  = (const float*)d_in[5];
    const float* b_hh  = (const float*)d_in[6];
    const float* W_lin = (const float*)d_in[7];
    const float* b_lin = (const float*)d_in[8];
    float* out = (float*)d_out;

    int B = in_sizes[1] / HH;   // 4096
    lstm_kernel<<<B / EE, 128>>>(x, h0, c0, W_ih, W_hh, b_ih, b_hh, W_lin, b_lin, out);
}

// round 14
// speedup vs baseline: 1.4787x; 1.4787x over previous
#include <cuda_runtime.h>
#include <cuda_bf16.h>

// Problem shape
#define TT 512
#define II 10
#define HH 32
#define EE 8                 // batch elements per block (= MMA N)
#define CH 32                // timesteps per x chunk
#define NCH (TT / CH)        // 16
#define XPAD 16              // padded feature dim (K for x part)
#define ESTR (CH * XPAD + 4) // x elem stride in floats (+4: bank-conflict skew)

typedef unsigned uu;

__device__ __forceinline__ uu tf32r(float f) {
    uu u; asm("cvt.rna.tf32.f32 %0, %1;" : "=r"(u) : "f"(f)); return u;
}
__device__ __forceinline__ float tanha(float x) {
    float r; asm("tanh.approx.f32 %0, %1;" : "=f"(r) : "f"(x)); return r;
}
// tf32: D += A(16x8) * B(8x8)
__device__ __forceinline__ void mma8(float& d0, float& d1, float& d2, float& d3,
                                     uu a0, uu a1, uu a2, uu a3, uu b0, uu b1) {
    asm("mma.sync.aligned.m16n8k8.row.col.f32.tf32.tf32.f32 "
        "{%0,%1,%2,%3},{%4,%5,%6,%7},{%8,%9},{%0,%1,%2,%3};"
        : "+f"(d0), "+f"(d1), "+f"(d2), "+f"(d3)
        : "r"(a0), "r"(a1), "r"(a2), "r"(a3), "r"(b0), "r"(b1));
}
// bf16: D += A(16x16) * B(16x8)
__device__ __forceinline__ void mma16(float& d0, float& d1, float& d2, float& d3,
                                      uu a0, uu a1, uu a2, uu a3, uu b0, uu b1) {
    asm("mma.sync.aligned.m16n8k16.row.col.f32.bf16.bf16.f32 "
        "{%0,%1,%2,%3},{%4,%5,%6,%7},{%8,%9},{%0,%1,%2,%3};"
        : "+f"(d0), "+f"(d1), "+f"(d2), "+f"(d3)
        : "r"(a0), "r"(a1), "r"(a2), "r"(a3), "r"(b0), "r"(b1));
}
// split (a,b) into packed bf16x2 hi word + residual lo word (a in low half)
__device__ __forceinline__ void bfsp(float a, float b, uu& hi, uu& lo) {
    __nv_bfloat16 xa = __float2bfloat16_rn(a), xb = __float2bfloat16_rn(b);
    hi = (uu)__bfloat16_as_ushort(xa) | ((uu)__bfloat16_as_ushort(xb) << 16);
    float ra = a - __bfloat162float(xa), rb = b - __bfloat162float(xb);
    lo = (uu)__bfloat16_as_ushort(__float2bfloat16_rn(ra))
       | ((uu)__bfloat16_as_ushort(__float2bfloat16_rn(rb)) << 16);
}
__device__ __forceinline__ unsigned sm32(const void* p) {
    return (unsigned)__cvta_generic_to_shared(p);
}
__device__ __forceinline__ void cp8(unsigned d, const void* s) {
    asm volatile("cp.async.ca.shared.global [%0], [%1], 8;" :: "r"(d), "l"(s));
}

// 128 threads, 8 elements/block, 4 blocks/SM (single wave for 512 CTAs).
// Warp w computes gate w (rows 32w..32w+31) for all 8 elements.
// W_hh in bf16 hi/lo (16-bit effective) via m16n8k16; h as packed bf16 {hi,lo};
// W_ih/x in tf32-hi via m16n8k8 (unchanged from the 328us baseline).
__global__ void __launch_bounds__(128, 4) lstm_kernel(
    const float* __restrict__ x,     const float* __restrict__ h0,
    const float* __restrict__ c0,    const float* __restrict__ W_ih,
    const float* __restrict__ W_hh,  const float* __restrict__ b_ih,
    const float* __restrict__ b_hh,  const float* __restrict__ W_lin,
    const float* __restrict__ b_lin, float* __restrict__ out)
{
    __shared__ __align__(16) float x_sh[2][EE * ESTR];     // ~33 KB
    __shared__ __align__(16) uint2 hfrag_sh[16][EE];       // 1 KB: [kpair][e]{hi,lo}
    __shared__ __align__(16) float gates_sh[4][HH][EE];    // post-activation

    const int tid  = threadIdx.x;
    const int w    = tid >> 5;          // warp = gate (0=i,1=f,2=g,3=o)
    const int lane = tid & 31;
    const int gid  = lane >> 2;         // MMA groupID (0..7) = element
    const int tig  = lane & 3;          // MMA thread-in-group
    const int base = blockIdx.x * EE;

    const float s     = (w == 2) ? 1.0f : 0.5f;   // sigmoid fold scale
    const float alpha = (w == 2) ? 1.0f : 0.5f;
    const float beta  = (w == 2) ? 0.0f : 0.5f;

    // ---- resident A fragments ----
    // W_hh: bf16 hi/lo, m16n8k16 layout: [mt][kt][reg]
    uu ahh[2][2][4], ahl[2][2][4];
    // W_ih: tf32-hi, m16n8k8 layout: [mt][kc][reg]
    uu ax[2][2][4];
    float bv[2][2];
    #pragma unroll
    for (int mt = 0; mt < 2; mt++) {
        #pragma unroll
        for (int kt = 0; kt < 2; kt++) {
            #pragma unroll
            for (int rg = 0; rg < 4; rg++) {
                int row = 32 * w + 16 * mt + 8 * (rg & 1) + gid;
                int col = 16 * kt + 2 * tig + 8 * (rg >> 1);
                bfsp(W_hh[row * HH + col] * s, W_hh[row * HH + col + 1] * s,
                     ahh[mt][kt][rg], ahl[mt][kt][rg]);
            }
        }
        #pragma unroll
        for (int rg = 0; rg < 4; rg++) {
            int row = 32 * w + 16 * mt + 8 * (rg & 1) + gid;
            #pragma unroll
            for (int kc = 0; kc < 2; kc++) {
                int j = 8 * kc + 4 * (rg >> 1) + tig;
                ax[mt][kc][rg] = tf32r((j < II) ? W_ih[row * II + j] * s : 0.0f);
            }
        }
        int r0 = 32 * w + 16 * mt + gid;
        bv[mt][0] = (b_ih[r0]     + b_hh[r0])     * s;
        bv[mt][1] = (b_ih[r0 + 8] + b_hh[r0 + 8]) * s;
    }

    // ---- per-thread state (l, e) and (l+16, e) ----
    const int e = tid & 7;
    const int l = tid >> 3;             // 0..15
    float c_a = c0[(base + e) * HH + l];
    float c_b = c0[(base + e) * HH + l + 16];
    float h_a = h0[(base + e) * HH + l];
    float h_b = h0[(base + e) * HH + l + 16];
    const float wl0 = W_lin[l];
    const float wl1 = W_lin[l + 16];

    // halfword indices into hfrag_sh for states k=l and k=l+16:
    // uint2 [kp][e]: hi word halves at (kp*8+e)*4 + {0,1}, lo at +{2,3}
    unsigned short* hb16 = reinterpret_cast<unsigned short*>(hfrag_sh);
    const int kpA  = l >> 1;
    const int half = l & 1;
    const int iHiA = (kpA * 8 + e) * 4 + half;
    const int iHiB = ((kpA + 8) * 8 + e) * 4 + half;

    {   // initial h fragments
        __nv_bfloat16 bh = __float2bfloat16_rn(h_a);
        hb16[iHiA] = __bfloat16_as_ushort(bh);
        hb16[iHiA + 2] = __bfloat16_as_ushort(
            __float2bfloat16_rn(h_a - __bfloat162float(bh)));
        __nv_bfloat16 bh2 = __float2bfloat16_rn(h_b);
        hb16[iHiB] = __bfloat16_as_ushort(bh2);
        hb16[iHiB + 2] = __bfloat16_as_ushort(
            __float2bfloat16_rn(h_b - __bfloat162float(bh2)));
    }

    // ---- x prefetch ----
    #define PREFETCH(chunk, buf)                                                  \
        do {                                                                      \
            for (int p = tid; p < EE * CH * 5; p += 128) {                        \
                int pe = p / (CH * 5);                                            \
                int r2 = p - pe * (CH * 5);                                       \
                int t  = r2 / 5;                                                  \
                int pj = r2 - t * 5;                                              \
                const float* src = x + ((size_t)(base + pe) * TT +                \
                                        (chunk) * CH + t) * II + 2 * pj;          \
                cp8(sm32(&x_sh[buf][pe * ESTR + t * XPAD + 2 * pj]), src);        \
            }                                                                     \
            asm volatile("cp.async.commit_group;");                               \
        } while (0)

    PREFETCH(0, 0);
    // zero pad columns j=10..15 in both buffers
    for (int p = tid; p < 2 * EE * CH * 6; p += 128) {
        int bf = p / (EE * CH * 6);
        int r  = p - bf * (EE * CH * 6);
        int pe = r / (CH * 6);
        int r2 = r - pe * (CH * 6);
        int t  = r2 / 6;
        int jj = 10 + (r2 - t * 6);
        x_sh[bf][pe * ESTR + t * XPAD + jj] = 0.0f;
    }
    asm volatile("cp.async.wait_group 0;");
    __syncthreads();

    // ---- recurrence ----
    for (int cix = 0; cix < NCH; cix++) {
        if (cix + 1 < NCH) { PREFETCH(cix + 1, (cix + 1) & 1); }
        const float* xc = x_sh[cix & 1];

        for (int tt = 0; tt < CH; tt++) {
            // h B-fragments (bf16 packed): per k-tile, 2 conflict-free LDS.64
            uint2 hu[4];                       // [kt*2 + which]
            #pragma unroll
            for (int kt = 0; kt < 2; kt++) {
                hu[2 * kt]     = hfrag_sh[8 * kt + tig][gid];
                hu[2 * kt + 1] = hfrag_sh[8 * kt + tig + 4][gid];
            }
            // x B-fragments: tf32-hi (4 LDS.32 + 4 cvt)
            const float* xe = xc + gid * ESTR + tt * XPAD;
            uu bxh[4];
            #pragma unroll
            for (int kc = 0; kc < 2; kc++) {
                bxh[2 * kc]     = tf32r(xe[8 * kc + tig]);
                bxh[2 * kc + 1] = tf32r(xe[8 * kc + tig + 4]);
            }

            #pragma unroll
            for (int mt = 0; mt < 2; mt++) {
                // chain1: Whh_hi*h_hi + x (bias init), depth 4
                float c10 = bv[mt][0], c11 = bv[mt][0];
                float c12 = bv[mt][1], c13 = bv[mt][1];
                // chain2: Whh_hi*h_lo, depth 2
                float c20 = 0.f, c21 = 0.f, c22 = 0.f, c23 = 0.f;
                // chain3: Whh_lo*h_hi, depth 2
                float c30 = 0.f, c31 = 0.f, c32 = 0.f, c33 = 0.f;

                #pragma unroll
                for (int kt = 0; kt < 2; kt++) {
                    mma16(c10, c11, c12, c13,
                          ahh[mt][kt][0], ahh[mt][kt][1], ahh[mt][kt][2], ahh[mt][kt][3],
                          hu[2 * kt].x, hu[2 * kt + 1].x);
                    mma16(c20, c21, c22, c23,
                          ahh[mt][kt][0], ahh[mt][kt][1], ahh[mt][kt][2], ahh[mt][kt][3],
                          hu[2 * kt].y, hu[2 * kt + 1].y);
                    mma16(c30, c31, c32, c33,
                          ahl[mt][kt][0], ahl[mt][kt][1], ahl[mt][kt][2], ahl[mt][kt][3],
                          hu[2 * kt].x, hu[2 * kt + 1].x);
                }
                #pragma unroll
                for (int kc = 0; kc < 2; kc++) {
                    mma8(c10, c11, c12, c13,
                         ax[mt][kc][0], ax[mt][kc][1], ax[mt][kc][2], ax[mt][kc][3],
                         bxh[2 * kc], bxh[2 * kc + 1]);
                }

                float d0 = (c10 + c20) + c30;
                float d1 = (c11 + c21) + c31;
                float d2 = (c12 + c22) + c32;
                float d3 = (c13 + c23) + c33;
                float a0v = fmaf(alpha, tanha(d0), beta);
                float a1v = fmaf(alpha, tanha(d1), beta);
                float a2v = fmaf(alpha, tanha(d2), beta);
                float a3v = fmaf(alpha, tanha(d3), beta);
                // rows gid / gid+8 within m-tile; cols (elems) 2tig, 2tig+1
                *reinterpret_cast<float2*>(&gates_sh[w][16 * mt + gid][2 * tig]) =
                    make_float2(a0v, a1v);
                *reinterpret_cast<float2*>(&gates_sh[w][16 * mt + 8 + gid][2 * tig]) =
                    make_float2(a2v, a3v);
            }
            __syncthreads();   // bar1: gates ready; all h reads complete

            // elementwise update: states (l, e) and (l+16, e)
            {
                float iv = gates_sh[0][l][e],      fv = gates_sh[1][l][e];
                float gv = gates_sh[2][l][e],      ov = gates_sh[3][l][e];
                c_a = fmaf(fv, c_a, iv * gv);
                h_a = ov * tanha(c_a);
                __nv_bfloat16 bh = __float2bfloat16_rn(h_a);
                hb16[iHiA] = __bfloat16_as_ushort(bh);
                hb16[iHiA + 2] = __bfloat16_as_ushort(
                    __float2bfloat16_rn(h_a - __bfloat162float(bh)));

                float iv2 = gates_sh[0][l + 16][e], fv2 = gates_sh[1][l + 16][e];
                float gv2 = gates_sh[2][l + 16][e], ov2 = gates_sh[3][l + 16][e];
                c_b = fmaf(fv2, c_b, iv2 * gv2);
                h_b = ov2 * tanha(c_b);
                __nv_bfloat16 bh2 = __float2bfloat16_rn(h_b);
                hb16[iHiB] = __bfloat16_as_ushort(bh2);
                hb16[iHiB + 2] = __bfloat16_as_ushort(
                    __float2bfloat16_rn(h_b - __bfloat162float(bh2)));
            }
            __syncthreads();   // bar2: new h visible
        }
        asm volatile("cp.async.wait_group 0;");
        __syncthreads();
    }

    // ---- final linear head ----
    float* scratch = &gates_sh[0][0][0];      // reuse as [EE][16]
    scratch[e * 16 + l] = fmaf(h_a, wl0, h_b * wl1);
    __syncthreads();
    if (tid < EE) {
        float sum = b_lin[0];
        #pragma unroll
        for (int q = 0; q < 16; q++) sum += scratch[tid * 16 + q];
        out[base + tid] = sum;
    }
}

extern "C" void kernel_launch(void* const* d_in, const int* in_sizes, int n_in,
                              void* d_out, int out_size) {
    const float* x     = (const float*)d_in[0];
    const float* h0    = (const float*)d_in[1];
    const float* c0    = (const float*)d_in[2];
    const float* W_ih  = (const float*)d_in[3];
    const float* W_hh  = (const float*)d_in[4];
    const float* b_ih  = (const float*)d_in[5];
    const float* b_hh  = (const float*)d_in[6];
    const float* W_lin = (const float*)d_in[7];
    const float* b_lin = (const float*)d_in[8];
    float* out = (float*)d_out;

    int B = in_sizes[1] / HH;   // 4096
    lstm_kernel<<<B / EE, 128>>>(x, h0, c0, W_ih, W_hh, b_ih, b_hh, W_lin, b_lin, out);
}